// round 2
// baseline (speedup 1.0000x reference)
#include <cuda_runtime.h>
#include <cuda_bf16.h>

// Problem constants
#define Bc 2
#define Fc 512
#define Hc 192
#define Wc 192
#define Tc 8

__device__ __forceinline__ float ndc_x(int wx) {
    return (2.0f * ((float)wx + 0.5f) - (float)Wc) / (float)Wc;
}
__device__ __forceinline__ float ndc_y(int hy) {
    return (2.0f * ((float)hy + 0.5f) - (float)Hc) / (float)Hc;
}

#define TILE 16
#define TX (Wc / TILE)   // 12
#define TY (Hc / TILE)   // 12

// Output layout (float32, concatenated in reference return order):
//   feature: (B, 9, H, W)  -> 663552
//   fim:     (B, H, W)     -> 73728  (cast to float)
//   dmap:    (B, H, W)     -> 73728
#define FEAT_OFF 0
#define FIM_OFF  (Bc * 9 * Hc * Wc)
#define DMAP_OFF (FIM_OFF + Bc * Hc * Wc)

__global__ __launch_bounds__(TILE * TILE, 4)
void rasterize_kernel(const float* __restrict__ faces,
                      const float* __restrict__ tex,
                      float* __restrict__ out)
{
    __shared__ float sx0[Fc], sy0[Fc], sx1[Fc], sy1[Fc], sx2[Fc], sy2[Fc];
    __shared__ float sinv[Fc], siz0[Fc], siz1[Fc], siz2[Fc];
    __shared__ int   slist[Fc];
    __shared__ int   scount;

    const int tid = threadIdx.y * TILE + threadIdx.x;
    const int bid = blockIdx.x;
    const int b   = bid / (TX * TY);
    const int t   = bid % (TX * TY);
    const int ty  = t / TX;
    const int tx  = t % TX;
    const int wx  = tx * TILE + threadIdx.x;
    const int hy  = ty * TILE + threadIdx.y;

    if (tid == 0) scount = 0;
    __syncthreads();

    // Tile NDC bounds (pixel centers; px/py increase with index)
    const float tpx0 = ndc_x(tx * TILE);
    const float tpx1 = ndc_x(tx * TILE + TILE - 1);
    const float tpy0 = ndc_y(ty * TILE);
    const float tpy1 = ndc_y(ty * TILE + TILE - 1);

    // Per-face precompute + bbox cull, cooperatively.
    const float* fb = faces + (size_t)b * Fc * 9;
    for (int f = tid; f < Fc; f += TILE * TILE) {
        const float* fp = fb + f * 9;
        float x0 = fp[0], y0 = fp[1], z0 = fp[2];
        float x1 = fp[3], y1 = fp[4], z1 = fp[5];
        float x2 = fp[6], y2 = fp[7], z2 = fp[8];

        float det = (x1 - x0) * (y2 - y0) - (x2 - x0) * (y1 - y0);
        bool ok = fabsf(det) > 1e-8f;

        sx0[f] = x0; sy0[f] = y0;
        sx1[f] = x1; sy1[f] = y1;
        sx2[f] = x2; sy2[f] = y2;
        sinv[f] = 1.0f / det;          // only consumed when ok
        siz0[f] = 1.0f / z0;
        siz1[f] = 1.0f / z1;
        siz2[f] = 1.0f / z2;

        float xmn = fminf(x0, fminf(x1, x2));
        float xmx = fmaxf(x0, fmaxf(x1, x2));
        float ymn = fminf(y0, fminf(y1, y2));
        float ymx = fmaxf(y0, fmaxf(y1, y2));

        if (ok && xmx >= tpx0 && xmn <= tpx1 && ymx >= tpy0 && ymn <= tpy1) {
            int p = atomicAdd(&scount, 1);
            slist[p] = f;
        }
    }
    __syncthreads();

    const int n = scount;
    const float px = ndc_x(wx);
    const float py = ndc_y(hy);

    float bestD = 100.0f;   // FAR
    int   bestF = -1;
    float bw0 = 0.0f, bw1 = 0.0f, bw2 = 0.0f;

    for (int i = 0; i < n; i++) {
        int f = slist[i];                 // uniform across warp -> broadcast LDS
        float x0 = sx0[f], y0 = sy0[f];
        float x1 = sx1[f], y1 = sy1[f];
        float x2 = sx2[f], y2 = sy2[f];
        float inv = sinv[f];

        float w0 = ((x1 - px) * (y2 - py) - (x2 - px) * (y1 - py)) * inv;
        float w1 = ((x2 - px) * (y0 - py) - (x0 - px) * (y2 - py)) * inv;
        float w2 = 1.0f - w0 - w1;

        if (w0 >= 0.0f && w1 >= 0.0f && w2 >= 0.0f) {
            float invd = w0 * siz0[f] + w1 * siz1[f] + w2 * siz2[f];
            float depth = (invd > 1e-8f) ? (1.0f / invd) : 100.0f;
            // valid & cand<best: depth<=FAR is implied by depth<bestD (bestD<=FAR)
            if (depth >= 0.5f && depth < bestD) {
                bestD = depth;
                bestF = f;
                bw0 = w0; bw1 = w1; bw2 = w2;
            }
        }
    }

    // Texture gather + output
    float feat[Tc];
    float mask;
    if (bestF >= 0) {
        const float4* tp = (const float4*)(tex + (size_t)(b * Fc + bestF) * 3 * Tc);
        float4 a0 = tp[0], a1 = tp[1];   // vertex 0, channels 0-3 / 4-7
        float4 b0 = tp[2], b1 = tp[3];   // vertex 1
        float4 c0 = tp[4], c1 = tp[5];   // vertex 2
        feat[0] = bw0 * a0.x + bw1 * b0.x + bw2 * c0.x;
        feat[1] = bw0 * a0.y + bw1 * b0.y + bw2 * c0.y;
        feat[2] = bw0 * a0.z + bw1 * b0.z + bw2 * c0.z;
        feat[3] = bw0 * a0.w + bw1 * b0.w + bw2 * c0.w;
        feat[4] = bw0 * a1.x + bw1 * b1.x + bw2 * c1.x;
        feat[5] = bw0 * a1.y + bw1 * b1.y + bw2 * c1.y;
        feat[6] = bw0 * a1.z + bw1 * b1.z + bw2 * c1.z;
        feat[7] = bw0 * a1.w + bw1 * b1.w + bw2 * c1.w;
        mask = 1.0f;
    } else {
        #pragma unroll
        for (int c = 0; c < Tc; c++) feat[c] = 0.0f;
        mask = 0.0f;
    }

    const int pix = (b * Hc + hy) * Wc + wx;
    #pragma unroll
    for (int c = 0; c < Tc; c++) {
        out[FEAT_OFF + ((size_t)(b * 9 + c) * Hc + hy) * Wc + wx] = feat[c];
    }
    out[FEAT_OFF + ((size_t)(b * 9 + 8) * Hc + hy) * Wc + wx] = mask;
    out[FIM_OFF + (size_t)pix - (size_t)b * Hc * Wc + (size_t)b * Hc * Wc] = (float)bestF;
    out[DMAP_OFF + (size_t)pix] = bestD;
}

extern "C" void kernel_launch(void* const* d_in, const int* in_sizes, int n_in,
                              void* d_out, int out_size) {
    const float* faces = (const float*)d_in[0];   // (B, F, 3, 3) float32
    const float* tex   = (const float*)d_in[1];   // (B, F, 3, T) float32
    float* out = (float*)d_out;

    dim3 block(TILE, TILE);
    dim3 grid(Bc * TX * TY);   // 288 tiles
    rasterize_kernel<<<grid, block>>>(faces, tex, out);
}

// round 3
// speedup vs baseline: 1.2610x; 1.2610x over previous
#include <cuda_runtime.h>
#include <cuda_bf16.h>

// Problem constants
#define Bc 2
#define Fc 512
#define Hc 192
#define Wc 192
#define Tc 8

#define TILE 16
#define TX (Wc / TILE)   // 12
#define TY (Hc / TILE)   // 12

__device__ __forceinline__ float ndc_x(int wx) {
    return (2.0f * ((float)wx + 0.5f) - (float)Wc) / (float)Wc;
}
__device__ __forceinline__ float ndc_y(int hy) {
    return (2.0f * ((float)hy + 0.5f) - (float)Hc) / (float)Hc;
}

// Output layout (float32, concatenated in reference return order):
//   feature: (B, 9, H, W) | fim: (B, H, W) as float | dmap: (B, H, W)
#define FEAT_OFF 0
#define FIM_OFF  (Bc * 9 * Hc * Wc)
#define DMAP_OFF (FIM_OFF + Bc * Hc * Wc)

__global__ __launch_bounds__(TILE * TILE, 6)
void rasterize_kernel(const float* __restrict__ faces,
                      const float* __restrict__ tex,
                      float* __restrict__ out)
{
    // Compacted, packed face data (written at cull time at the compacted slot):
    //   sq0 = (x0, y0, x1, y1)
    //   sq1 = (x2, y2, inv_det, face_idx_bits)
    //   sq2 = (1/z0, 1/z1, 1/z2, unused)
    __shared__ float4 sq0[Fc], sq1[Fc], sq2[Fc];
    __shared__ int    scount;

    const int tid = threadIdx.y * TILE + threadIdx.x;
    const int bid = blockIdx.x;
    const int b   = bid / (TX * TY);
    const int t   = bid % (TX * TY);
    const int ty  = t / TX;
    const int tx  = t % TX;
    const int wx  = tx * TILE + threadIdx.x;
    const int hy  = ty * TILE + threadIdx.y;

    if (tid == 0) scount = 0;
    __syncthreads();

    // Tile NDC bounds (pixel centers; px/py increase with index)
    const float tpx0 = ndc_x(tx * TILE);
    const float tpx1 = ndc_x(tx * TILE + TILE - 1);
    const float tpy0 = ndc_y(ty * TILE);
    const float tpy1 = ndc_y(ty * TILE + TILE - 1);

    // Per-face precompute + bbox cull, cooperatively; compact into packed smem.
    const float* fb = faces + (size_t)b * Fc * 9;
    #pragma unroll 2
    for (int f = tid; f < Fc; f += TILE * TILE) {
        const float* fp = fb + f * 9;
        float x0 = fp[0], y0 = fp[1], z0 = fp[2];
        float x1 = fp[3], y1 = fp[4], z1 = fp[5];
        float x2 = fp[6], y2 = fp[7], z2 = fp[8];

        float det = (x1 - x0) * (y2 - y0) - (x2 - x0) * (y1 - y0);
        bool ok = fabsf(det) > 1e-8f;

        float xmn = fminf(x0, fminf(x1, x2));
        float xmx = fmaxf(x0, fmaxf(x1, x2));
        float ymn = fminf(y0, fminf(y1, y2));
        float ymx = fmaxf(y0, fmaxf(y1, y2));

        if (ok && xmx >= tpx0 && xmn <= tpx1 && ymx >= tpy0 && ymn <= tpy1) {
            int p = atomicAdd(&scount, 1);
            sq0[p] = make_float4(x0, y0, x1, y1);
            sq1[p] = make_float4(x2, y2, 1.0f / det, __int_as_float(f));
            sq2[p] = make_float4(1.0f / z0, 1.0f / z1, 1.0f / z2, 0.0f);
        }
    }
    __syncthreads();

    const int n = scount;
    const float px = ndc_x(wx);
    const float py = ndc_y(hy);

    // Track max inverse-depth instead of min depth (monotone equivalent):
    //   depth < bestD        <=> invd > bestInv   (positive range)
    //   depth >= NEAR (0.5)  <=> invd <= 2.0
    //   depth <  FAR  (100)  <=> invd > 0.01   (depth==FAR never counts as covered)
    float bestInv = 0.01f;
    int   bestF   = -1;
    float bw0 = 0.0f, bw1 = 0.0f, bw2 = 0.0f;

    #pragma unroll 4
    for (int i = 0; i < n; i++) {
        float4 q0 = sq0[i];   // uniform address -> LDS.128 broadcast
        float4 q1 = sq1[i];
        float4 q2 = sq2[i];

        float w0 = ((q0.z - px) * (q1.y - py) - (q1.x - px) * (q0.w - py)) * q1.z;
        float w1 = ((q1.x - px) * (q0.y - py) - (q0.x - px) * (q1.y - py)) * q1.z;
        float w2 = 1.0f - w0 - w1;

        float invd = w0 * q2.x + w1 * q2.y + w2 * q2.z;

        bool hit = (w0 >= 0.0f) & (w1 >= 0.0f) & (w2 >= 0.0f)
                 & (invd > bestInv) & (invd <= 2.0f);

        // branchless update (compiler -> FSETP + FSEL/SEL chain)
        bestInv = hit ? invd : bestInv;
        bestF   = hit ? __float_as_int(q1.w) : bestF;
        bw0     = hit ? w0 : bw0;
        bw1     = hit ? w1 : bw1;
        bw2     = hit ? w2 : bw2;
    }

    const bool covered = (bestF >= 0);
    const float bestD = covered ? (1.0f / bestInv) : 100.0f;

    // Texture gather + output
    float feat[Tc];
    float mask;
    if (covered) {
        const float4* tp = (const float4*)(tex + (size_t)(b * Fc + bestF) * 3 * Tc);
        float4 a0 = tp[0], a1 = tp[1];
        float4 b0 = tp[2], b1 = tp[3];
        float4 c0 = tp[4], c1 = tp[5];
        feat[0] = bw0 * a0.x + bw1 * b0.x + bw2 * c0.x;
        feat[1] = bw0 * a0.y + bw1 * b0.y + bw2 * c0.y;
        feat[2] = bw0 * a0.z + bw1 * b0.z + bw2 * c0.z;
        feat[3] = bw0 * a0.w + bw1 * b0.w + bw2 * c0.w;
        feat[4] = bw0 * a1.x + bw1 * b1.x + bw2 * c1.x;
        feat[5] = bw0 * a1.y + bw1 * b1.y + bw2 * c1.y;
        feat[6] = bw0 * a1.z + bw1 * b1.z + bw2 * c1.z;
        feat[7] = bw0 * a1.w + bw1 * b1.w + bw2 * c1.w;
        mask = 1.0f;
    } else {
        #pragma unroll
        for (int c = 0; c < Tc; c++) feat[c] = 0.0f;
        mask = 0.0f;
    }

    const int pix = (b * Hc + hy) * Wc + wx;
    #pragma unroll
    for (int c = 0; c < Tc; c++) {
        out[FEAT_OFF + ((size_t)(b * 9 + c) * Hc + hy) * Wc + wx] = feat[c];
    }
    out[FEAT_OFF + ((size_t)(b * 9 + 8) * Hc + hy) * Wc + wx] = mask;
    out[FIM_OFF  + (size_t)pix] = (float)bestF;
    out[DMAP_OFF + (size_t)pix] = bestD;
}

extern "C" void kernel_launch(void* const* d_in, const int* in_sizes, int n_in,
                              void* d_out, int out_size) {
    const float* faces = (const float*)d_in[0];   // (B, F, 3, 3) float32
    const float* tex   = (const float*)d_in[1];   // (B, F, 3, T) float32
    float* out = (float*)d_out;

    dim3 block(TILE, TILE);
    dim3 grid(Bc * TX * TY);   // 288 tiles
    rasterize_kernel<<<grid, block>>>(faces, tex, out);
}